// round 2
// baseline (speedup 1.0000x reference)
#include <cuda_runtime.h>
#include <cstdint>
#include <math.h>

#define HH 128
#define WW 128
#define HW 16384
#define CC 16
#define NPTS 32
#define NLINES (5 * HW)
#define LOI_FLOATS (NLINES * (CC * NPTS))   // 81920 * 512 = 41,943,040
#define J_OFF LOI_FLOATS
#define S_OFF (LOI_FLOATS + 600)
#define TOPK 300
#define SORT_N 4096

// Scratch (allocation-free rules: __device__ globals)
__device__ float4 g_ft4[HW * 4];                 // features transposed to (H,W,C), C contiguous
__device__ unsigned long long g_keys[SORT_N];    // NMS candidate keys
__device__ int g_cnt;

// ---------------------------------------------------------------------------
// Kernel 1: transpose features (C,H,W) -> (H,W,C) as float4 groups; reset counter
// ---------------------------------------------------------------------------
__global__ void transpose_kernel(const float* __restrict__ f) {
    int p = blockIdx.x * blockDim.x + threadIdx.x;
    if (p == 0) g_cnt = 0;
    if (p < HW) {
#pragma unroll
        for (int j = 0; j < 4; j++) {
            float4 v;
            v.x = f[(4 * j + 0) * HW + p];
            v.y = f[(4 * j + 1) * HW + p];
            v.z = f[(4 * j + 2) * HW + p];
            v.w = f[(4 * j + 3) * HW + p];
            g_ft4[p * 4 + j] = v;
        }
    }
}

// ---------------------------------------------------------------------------
// Kernel 2: fused HAFM decode + LOI bilinear sampling. One warp per line.
// lane = t-index (0..31). Output layout out[l*512 + c*32 + t].
// ---------------------------------------------------------------------------
__global__ void __launch_bounds__(256) loi_kernel(
    const float* __restrict__ md,    // (3,H,W)
    const float* __restrict__ dis,   // (H,W)
    const float* __restrict__ res,   // (H,W)
    float* __restrict__ out)
{
    const int warp = threadIdx.x >> 5;
    const int lane = threadIdx.x & 31;
    const int l = blockIdx.x * (blockDim.x >> 5) + warp;
    if (l >= NLINES) return;

    const int r = l / HW;          // residual index 0..4, sign = r-2
    const int p = l - r * HW;      // pixel
    const int yi = p >> 7;
    const int xi = p & 127;

    // --- HAFM decoding (warp-uniform math; every lane computes the same) ---
    float dval = dis[p] + res[p] * (float)(r - 2);
    dval = fminf(fmaxf(dval, 0.0f), 1.0f);
    const float md0 = md[p];
    const float md1 = md[HW + p];
    const float md2 = md[2 * HW + p];

    const float md_un = (md0 - 0.5f) * 6.2831853071795864f;   // 2*pi
    float ss, cs;
    sincosf(md_un, &ss, &cs);
    const float yst = tanf(md1 * 1.5707963267948966f);
    const float yed = tanf(-md2 * 1.5707963267948966f);
    const float ds = dval * 5.0f;   // DIST_THRESHOLD

    const float fx = (float)xi, fy = (float)yi;
    const float ux = fminf(fmaxf((cs - ss * yst) * ds + fx, 0.0f), 127.0f);
    const float uy = fminf(fmaxf((ss + cs * yst) * ds + fy, 0.0f), 127.0f);
    const float vx = fminf(fmaxf((cs - ss * yed) * ds + fx, 0.0f), 127.0f);
    const float vy = fminf(fmaxf((ss + cs * yed) * ds + fy, 0.0f), 127.0f);

    // --- point for this lane ---
    const float t = (float)lane * (1.0f / 31.0f);
    const float px = ux * t + vx * (1.0f - t) - 0.5f;
    const float py = uy * t + vy * (1.0f - t) - 0.5f;

    const float px0 = fminf(fmaxf(floorf(px), 0.0f), 127.0f);
    const float py0 = fminf(fmaxf(floorf(py), 0.0f), 127.0f);
    const float px1 = fminf(px0 + 1.0f, 127.0f);
    const float py1 = fminf(py0 + 1.0f, 127.0f);

    const int ix0 = (int)px0, iy0 = (int)py0;
    const int ix1 = (int)px1, iy1 = (int)py1;

    const float w00 = (py1 - py) * (px1 - px);
    const float w10 = (py - py0) * (px1 - px);
    const float w01 = (py1 - py) * (px - px0);
    const float w11 = (py - py0) * (px - px0);

    const float4* __restrict__ f00 = g_ft4 + (iy0 * WW + ix0) * 4;
    const float4* __restrict__ f10 = g_ft4 + (iy1 * WW + ix0) * 4;
    const float4* __restrict__ f01 = g_ft4 + (iy0 * WW + ix1) * 4;
    const float4* __restrict__ f11 = g_ft4 + (iy1 * WW + ix1) * 4;

    float acc[CC];
#pragma unroll
    for (int j = 0; j < 4; j++) {
        float4 a = f00[j];
        float4 b = f10[j];
        float4 c = f01[j];
        float4 d = f11[j];
        acc[4 * j + 0] = w00 * a.x + w10 * b.x + w01 * c.x + w11 * d.x;
        acc[4 * j + 1] = w00 * a.y + w10 * b.y + w01 * c.y + w11 * d.y;
        acc[4 * j + 2] = w00 * a.z + w10 * b.z + w01 * c.z + w11 * d.z;
        acc[4 * j + 3] = w00 * a.w + w10 * b.w + w01 * c.w + w11 * d.w;
    }

    float* __restrict__ o = out + (size_t)l * (CC * NPTS) + lane;
#pragma unroll
    for (int c = 0; c < CC; c++)
        o[c * NPTS] = acc[c];   // 32 lanes -> 128B coalesced store per c
}

// ---------------------------------------------------------------------------
// Kernel 3: 3x3 NMS; compact positive local maxima into key list.
// key = (float_bits << 32) | (0xFFFFFFFF - idx)  -> desc sort = value desc, idx asc
// ---------------------------------------------------------------------------
__global__ void nms_kernel(const float* __restrict__ jloc) {
    int p = blockIdx.x * blockDim.x + threadIdx.x;
    if (p >= HW) return;
    int y = p >> 7, x = p & 127;
    float a = jloc[p];
    float m = -INFINITY;
#pragma unroll
    for (int dy = -1; dy <= 1; dy++) {
#pragma unroll
        for (int dx = -1; dx <= 1; dx++) {
            int yy = y + dy, xx = x + dx;
            if (yy >= 0 && yy < HH && xx >= 0 && xx < WW)
                m = fmaxf(m, jloc[yy * WW + xx]);
        }
    }
    if (a == m && a > 0.0f) {
        int pos = atomicAdd(&g_cnt, 1);
        if (pos < SORT_N) {
            unsigned long long key =
                ((unsigned long long)__float_as_uint(a) << 32) |
                (unsigned long long)(0xFFFFFFFFu - (unsigned)p);
            g_keys[pos] = key;
        }
    }
}

// ---------------------------------------------------------------------------
// Kernel 4: single-block bitonic sort (descending) of candidates, emit top-300.
// ---------------------------------------------------------------------------
__global__ void __launch_bounds__(1024) topk_kernel(
    const float* __restrict__ joff, float* __restrict__ out)
{
    __shared__ unsigned long long s[SORT_N];
    const int tid = threadIdx.x;
    int cnt = g_cnt;
    if (cnt > SORT_N) cnt = SORT_N;
    for (int i = tid; i < SORT_N; i += 1024)
        s[i] = (i < cnt) ? g_keys[i] : 0ULL;
    __syncthreads();

    for (int k = 2; k <= SORT_N; k <<= 1) {
        for (int j = k >> 1; j > 0; j >>= 1) {
            for (int i = tid; i < SORT_N; i += 1024) {
                int ixj = i ^ j;
                if (ixj > i) {
                    unsigned long long a = s[i], b = s[ixj];
                    bool desc = ((i & k) == 0);
                    if ((a < b) == desc) { s[i] = b; s[ixj] = a; }
                }
            }
            __syncthreads();
        }
    }

    if (tid < TOPK) {
        unsigned long long key = s[tid];
        unsigned idx = 0xFFFFFFFFu - (unsigned)(key & 0xFFFFFFFFull);
        float val = __uint_as_float((unsigned)(key >> 32));
        float fy = (float)(idx >> 7);
        float fx = (float)(idx & 127);
        float jx = fx + joff[idx] + 0.5f;        // joff[0] = x offset
        float jy = fy + joff[HW + idx] + 0.5f;   // joff[1] = y offset
        out[J_OFF + 2 * tid + 0] = jx;
        out[J_OFF + 2 * tid + 1] = jy;
        out[S_OFF + tid] = val;
    }
}

// ---------------------------------------------------------------------------
extern "C" void kernel_launch(void* const* d_in, const int* in_sizes, int n_in,
                              void* d_out, int out_size) {
    const float* md   = (const float*)d_in[0];   // (1,3,128,128)
    const float* dis  = (const float*)d_in[1];   // (1,1,128,128)
    const float* res  = (const float*)d_in[2];   // (1,1,128,128)
    const float* feat = (const float*)d_in[3];   // (16,128,128)
    const float* jloc = (const float*)d_in[4];   // (1,128,128)
    const float* joff = (const float*)d_in[5];   // (2,128,128)
    float* out = (float*)d_out;

    transpose_kernel<<<(HW + 255) / 256, 256>>>(feat);
    loi_kernel<<<NLINES / 8, 256>>>(md, dis, res, out);
    nms_kernel<<<(HW + 255) / 256, 256>>>(jloc);
    topk_kernel<<<1, 1024>>>(joff, out);
}